// round 1
// baseline (speedup 1.0000x reference)
#include <cuda_runtime.h>

#define B_   32
#define C_   256
#define H_   64
#define W_   64
#define HW_  4096            // H*W
#define BC_  8192            // B*C
#define HID_ 64
#define KSZ_ 5

// Scratch (allocation-free rule: __device__ globals)
__device__ float g_mean[BC_];
__device__ float g_i4v[BC_];    // 1 / (4*(var + 1e-4))
__device__ float g_s2[BC_];     // sum over HW of x*sigmoid(energy)
__device__ float g_gate[BC_];   // ECA gate
__device__ float g_alpha[BC_];  // fusion gate

__device__ __forceinline__ float sigm(float v) {
    return 1.0f / (1.0f + __expf(-v));
}

// ---------------------------------------------------------------------------
// Kernel 1: per-(b,c) stats + SimAM-weighted sum, single HBM read of x.
// One CTA per row of 4096 floats; 256 threads x 16 floats kept in registers.
// ---------------------------------------------------------------------------
__global__ void __launch_bounds__(256) stat_kernel(const float* __restrict__ x)
{
    const int row = blockIdx.x;                    // b*C + c
    const int t   = threadIdx.x;
    const float4* xr = (const float4*)(x + (size_t)row * HW_);

    float4 v[4];
#pragma unroll
    for (int j = 0; j < 4; j++) v[j] = xr[t + j * 256];

    float s = 0.f, ss = 0.f;
#pragma unroll
    for (int j = 0; j < 4; j++) {
        float4 q = v[j];
        s  += (q.x + q.y) + (q.z + q.w);
        ss += q.x * q.x + q.y * q.y + q.z * q.z + q.w * q.w;
    }
#pragma unroll
    for (int o = 16; o > 0; o >>= 1) {
        s  += __shfl_xor_sync(0xffffffffu, s,  o);
        ss += __shfl_xor_sync(0xffffffffu, ss, o);
    }

    __shared__ float shS[8], shQ[8], bcast[2];
    const int w = t >> 5, l = t & 31;
    if (l == 0) { shS[w] = s; shQ[w] = ss; }
    __syncthreads();
    if (t == 0) {
        float S = 0.f, Q = 0.f;
#pragma unroll
        for (int i = 0; i < 8; i++) { S += shS[i]; Q += shQ[i]; }
        const float mean = S * (1.0f / HW_);
        const float var  = (Q - (float)HW_ * mean * mean) * (1.0f / (HW_ - 1));
        const float i4v  = 1.0f / (4.0f * (var + 1e-4f));
        bcast[0] = mean; bcast[1] = i4v;
        g_mean[row] = mean;
        g_i4v[row]  = i4v;
    }
    __syncthreads();
    const float mean = bcast[0];
    const float i4v  = bcast[1];

    float s2 = 0.f;
#pragma unroll
    for (int j = 0; j < 4; j++) {
        float4 q = v[j];
        float d;
        d = q.x - mean; s2 += q.x * sigm(fmaf(d * d, i4v, 0.5f));
        d = q.y - mean; s2 += q.y * sigm(fmaf(d * d, i4v, 0.5f));
        d = q.z - mean; s2 += q.z * sigm(fmaf(d * d, i4v, 0.5f));
        d = q.w - mean; s2 += q.w * sigm(fmaf(d * d, i4v, 0.5f));
    }
#pragma unroll
    for (int o = 16; o > 0; o >>= 1)
        s2 += __shfl_xor_sync(0xffffffffu, s2, o);
    if (l == 0) shS[w] = s2;
    __syncthreads();
    if (t == 0) {
        float S = 0.f;
#pragma unroll
        for (int i = 0; i < 8; i++) S += shS[i];
        g_s2[row] = S;
    }
}

// ---------------------------------------------------------------------------
// Kernel 2: per-batch ECA conv + fusion MLP (tiny). One CTA per batch.
// ---------------------------------------------------------------------------
__global__ void __launch_bounds__(256) gate_kernel(const float* __restrict__ cw,
                                                   const float* __restrict__ w1,
                                                   const float* __restrict__ w2)
{
    const int b = blockIdx.x;
    const int c = threadIdx.x;        // 0..255
    const int idx = b * C_ + c;

    __shared__ float m[C_], gap[C_], hid[HID_];
    m[c] = g_mean[idx];
    __syncthreads();

    // ECA: cross-correlation over channel dim, zero-padded, K=5
    float y = 0.f;
#pragma unroll
    for (int k = 0; k < KSZ_; k++) {
        const int cc = c + k - (KSZ_ - 1) / 2;
        const float mv = (cc >= 0 && cc < C_) ? m[cc] : 0.f;
        y = fmaf(mv, cw[k], y);
    }
    const float gate = sigm(y);
    g_gate[idx] = gate;
    gap[c] = fmaf(gate, m[c], g_s2[idx] * (1.0f / HW_));
    __syncthreads();

    // hid[j] = relu(sum_c gap[c] * w1[j, c]),  w1 is [HID, C] row-major
    if (c < HID_) {
        float h = 0.f;
        const float* w1r = w1 + c * C_;
#pragma unroll 8
        for (int i = 0; i < C_; i++) h = fmaf(gap[i], w1r[i], h);
        hid[c] = fmaxf(h, 0.f);
    }
    __syncthreads();

    // alpha[c] = sigmoid(sum_j hid[j] * w2[c, j]), w2 is [C, HID] row-major
    float a = 0.f;
    const float* w2r = w2 + c * HID_;
#pragma unroll 8
    for (int j = 0; j < HID_; j++) a = fmaf(hid[j], w2r[j], a);
    g_alpha[idx] = sigm(a);
}

// ---------------------------------------------------------------------------
// Kernel 3: out = x * (alpha*sigmoid(energy) + (1-alpha)*gate), per-row.
// ---------------------------------------------------------------------------
__global__ void __launch_bounds__(256) out_kernel(const float* __restrict__ x,
                                                  float* __restrict__ out)
{
    const int row = blockIdx.x;
    const int t   = threadIdx.x;

    const float mean  = g_mean[row];
    const float i4v   = g_i4v[row];
    const float alpha = g_alpha[row];
    const float og    = (1.0f - alpha) * g_gate[row];

    const float4* xr = (const float4*)(x   + (size_t)row * HW_);
    float4*       orw = (float4*)     (out + (size_t)row * HW_);

#pragma unroll
    for (int j = 0; j < 4; j++) {
        float4 q = xr[t + j * 256];
        float4 r;
        float d;
        d = q.x - mean; r.x = q.x * fmaf(alpha, sigm(fmaf(d * d, i4v, 0.5f)), og);
        d = q.y - mean; r.y = q.y * fmaf(alpha, sigm(fmaf(d * d, i4v, 0.5f)), og);
        d = q.z - mean; r.z = q.z * fmaf(alpha, sigm(fmaf(d * d, i4v, 0.5f)), og);
        d = q.w - mean; r.w = q.w * fmaf(alpha, sigm(fmaf(d * d, i4v, 0.5f)), og);
        orw[t + j * 256] = r;
    }
}

// ---------------------------------------------------------------------------
extern "C" void kernel_launch(void* const* d_in, const int* in_sizes, int n_in,
                              void* d_out, int out_size)
{
    const float* x  = (const float*)d_in[0];   // [B, C, H, W]
    const float* cw = (const float*)d_in[1];   // [1, 1, 5]
    const float* w1 = (const float*)d_in[2];   // [HID, C]
    const float* w2 = (const float*)d_in[3];   // [C, HID]
    float* out = (float*)d_out;

    stat_kernel<<<BC_, 256>>>(x);
    gate_kernel<<<B_, 256>>>(cw, w1, w2);
    out_kernel<<<BC_, 256>>>(x, out);
}

// round 2
// speedup vs baseline: 1.1670x; 1.1670x over previous
#include <cuda_runtime.h>

#define B_   32
#define C_   256
#define H_   64
#define W_   64
#define HW_  4096            // H*W
#define BC_  8192            // B*C
#define HID_ 64
#define KSZ_ 5

// Scratch (allocation-free rule: __device__ globals)
__device__ float g_mean[BC_];
__device__ float g_h4v[BC_];    // 0.5 / (4*(var + 1e-4))
__device__ float g_s2[BC_];     // sum over HW of x*sigmoid(energy)
__device__ float g_gate[BC_];   // ECA gate
__device__ float g_alpha[BC_];  // fusion gate

__device__ __forceinline__ float sigm(float v) {          // accurate-ish, tiny kernel only
    return 1.0f / (1.0f + __expf(-v));
}
__device__ __forceinline__ float tanh_fast(float v) {     // MUFU.TANH, 1 MUFU
    float r;
    asm("tanh.approx.f32 %0, %1;" : "=f"(r) : "f"(v));
    return r;
}

// ---------------------------------------------------------------------------
// Kernel 1: per-(b,c) stats + SimAM-weighted sum, single HBM read of x.
// sigmoid(e) = 0.5*tanh(e/2)+0.5, e/2 = d*d*h4v + 0.25
// ---------------------------------------------------------------------------
__global__ void __launch_bounds__(256) stat_kernel(const float* __restrict__ x)
{
    const int row = blockIdx.x;                    // b*C + c
    const int t   = threadIdx.x;
    const float4* xr = (const float4*)(x + (size_t)row * HW_);

    float4 v[4];
#pragma unroll
    for (int j = 0; j < 4; j++) v[j] = xr[t + j * 256];

    float s = 0.f, ss = 0.f;
#pragma unroll
    for (int j = 0; j < 4; j++) {
        float4 q = v[j];
        s  += (q.x + q.y) + (q.z + q.w);
        ss += q.x * q.x + q.y * q.y + q.z * q.z + q.w * q.w;
    }
#pragma unroll
    for (int o = 16; o > 0; o >>= 1) {
        s  += __shfl_xor_sync(0xffffffffu, s,  o);
        ss += __shfl_xor_sync(0xffffffffu, ss, o);
    }

    __shared__ float shS[8], shQ[8], bcast[2];
    const int w = t >> 5, l = t & 31;
    if (l == 0) { shS[w] = s; shQ[w] = ss; }
    __syncthreads();
    if (t == 0) {
        float S = 0.f, Q = 0.f;
#pragma unroll
        for (int i = 0; i < 8; i++) { S += shS[i]; Q += shQ[i]; }
        const float mean = S * (1.0f / HW_);
        const float var  = (Q - (float)HW_ * mean * mean) * (1.0f / (HW_ - 1));
        const float h4v  = 0.125f / (var + 1e-4f);   // = 0.5 * 1/(4(var+eps))
        bcast[0] = mean; bcast[1] = h4v;
        g_mean[row] = mean;
        g_h4v[row]  = h4v;
    }
    __syncthreads();
    const float mean = bcast[0];
    const float h4v  = bcast[1];

    float s2 = 0.f;
#pragma unroll
    for (int j = 0; j < 4; j++) {
        float4 q = v[j];
        float d, th;
        d = q.x - mean; th = tanh_fast(fmaf(d * d, h4v, 0.25f)); s2 = fmaf(q.x, fmaf(th, 0.5f, 0.5f), s2);
        d = q.y - mean; th = tanh_fast(fmaf(d * d, h4v, 0.25f)); s2 = fmaf(q.y, fmaf(th, 0.5f, 0.5f), s2);
        d = q.z - mean; th = tanh_fast(fmaf(d * d, h4v, 0.25f)); s2 = fmaf(q.z, fmaf(th, 0.5f, 0.5f), s2);
        d = q.w - mean; th = tanh_fast(fmaf(d * d, h4v, 0.25f)); s2 = fmaf(q.w, fmaf(th, 0.5f, 0.5f), s2);
    }
#pragma unroll
    for (int o = 16; o > 0; o >>= 1)
        s2 += __shfl_xor_sync(0xffffffffu, s2, o);
    if (l == 0) shS[w] = s2;
    __syncthreads();
    if (t == 0) {
        float S = 0.f;
#pragma unroll
        for (int i = 0; i < 8; i++) S += shS[i];
        g_s2[row] = S;
    }
}

// ---------------------------------------------------------------------------
// Kernel 2: per-batch ECA conv + fusion MLP (tiny). One CTA per batch.
// ---------------------------------------------------------------------------
__global__ void __launch_bounds__(256) gate_kernel(const float* __restrict__ cw,
                                                   const float* __restrict__ w1,
                                                   const float* __restrict__ w2)
{
    const int b = blockIdx.x;
    const int c = threadIdx.x;        // 0..255
    const int idx = b * C_ + c;

    __shared__ float m[C_], gap[C_], hid[HID_];
    m[c] = g_mean[idx];
    __syncthreads();

    // ECA: cross-correlation over channel dim, zero-padded, K=5
    float y = 0.f;
#pragma unroll
    for (int k = 0; k < KSZ_; k++) {
        const int cc = c + k - (KSZ_ - 1) / 2;
        const float mv = (cc >= 0 && cc < C_) ? m[cc] : 0.f;
        y = fmaf(mv, cw[k], y);
    }
    const float gate = sigm(y);
    g_gate[idx] = gate;
    gap[c] = fmaf(gate, m[c], g_s2[idx] * (1.0f / HW_));
    __syncthreads();

    // hid[j] = relu(sum_c gap[c] * w1[j, c]),  w1 is [HID, C] row-major
    if (c < HID_) {
        float h = 0.f;
        const float* w1r = w1 + c * C_;
#pragma unroll 8
        for (int i = 0; i < C_; i++) h = fmaf(gap[i], w1r[i], h);
        hid[c] = fmaxf(h, 0.f);
    }
    __syncthreads();

    // alpha[c] = sigmoid(sum_j hid[j] * w2[c, j]), w2 is [C, HID] row-major
    float a = 0.f;
    const float* w2r = w2 + c * HID_;
#pragma unroll 8
    for (int j = 0; j < HID_; j++) a = fmaf(hid[j], w2r[j], a);
    g_alpha[idx] = sigm(a);
}

// ---------------------------------------------------------------------------
// Kernel 3: out = x * (alpha*sigmoid(energy) + (1-alpha)*gate)
//   alpha*sigm + og = fma(alpha/2, tanh(e/2), alpha/2 + og)
// Rows walked in REVERSE so the L2-resident tail from stat_kernel hits first.
// Streaming stores (st.global.cs) keep output from evicting x in L2.
// ---------------------------------------------------------------------------
__global__ void __launch_bounds__(256) out_kernel(const float* __restrict__ x,
                                                  float* __restrict__ out)
{
    const int row = BC_ - 1 - blockIdx.x;
    const int t   = threadIdx.x;

    const float mean  = g_mean[row];
    const float h4v   = g_h4v[row];
    const float alpha = g_alpha[row];
    const float a2    = 0.5f * alpha;
    const float a3    = fmaf(1.0f - alpha, g_gate[row], a2);

    const float4* xr = (const float4*)(x   + (size_t)row * HW_);
    float4*       ow = (float4*)     (out + (size_t)row * HW_);

#pragma unroll
    for (int j = 0; j < 4; j++) {
        float4 q = xr[t + j * 256];
        float4 r;
        float d, th;
        d = q.x - mean; th = tanh_fast(fmaf(d * d, h4v, 0.25f)); r.x = q.x * fmaf(a2, th, a3);
        d = q.y - mean; th = tanh_fast(fmaf(d * d, h4v, 0.25f)); r.y = q.y * fmaf(a2, th, a3);
        d = q.z - mean; th = tanh_fast(fmaf(d * d, h4v, 0.25f)); r.z = q.z * fmaf(a2, th, a3);
        d = q.w - mean; th = tanh_fast(fmaf(d * d, h4v, 0.25f)); r.w = q.w * fmaf(a2, th, a3);
        __stcs(&ow[t + j * 256], r);
    }
}

// ---------------------------------------------------------------------------
extern "C" void kernel_launch(void* const* d_in, const int* in_sizes, int n_in,
                              void* d_out, int out_size)
{
    const float* x  = (const float*)d_in[0];   // [B, C, H, W]
    const float* cw = (const float*)d_in[1];   // [1, 1, 5]
    const float* w1 = (const float*)d_in[2];   // [HID, C]
    const float* w2 = (const float*)d_in[3];   // [C, HID]
    float* out = (float*)d_out;

    stat_kernel<<<BC_, 256>>>(x);
    gate_kernel<<<B_, 256>>>(cw, w1, w2);
    out_kernel<<<BC_, 256>>>(x, out);
}

// round 3
// speedup vs baseline: 1.2237x; 1.0486x over previous
#include <cuda_runtime.h>

#define B_   32
#define C_   256
#define H_   64
#define W_   64
#define HW_  4096            // H*W
#define BC_  8192            // B*C
#define HID_ 64
#define KSZ_ 5

// Scratch (allocation-free rule: __device__ globals)
__device__ float g_mean[BC_];
__device__ float g_h4v[BC_];    // 0.125 / (var + 1e-4)
__device__ float g_s2[BC_];     // sum over HW of x*sigmoid(energy)
__device__ float g_gate[BC_];   // ECA gate
__device__ float g_alpha[BC_];  // fusion gate

__device__ __forceinline__ float sigm(float v) {          // tiny kernel only
    return 1.0f / (1.0f + __expf(-v));
}
__device__ __forceinline__ float tanh_fast(float v) {     // MUFU.TANH, 1 MUFU
    float r;
    asm("tanh.approx.f32 %0, %1;" : "=f"(r) : "f"(v));
    return r;
}

// ---------------------------------------------------------------------------
// Kernel 1: per-(b,c) stats + SimAM-weighted sum.
// Phase 1 loads x (fills L1), phase 2 RE-READS from L1 instead of holding
// 16 registers across the barrier -> low reg count, high occupancy.
// ---------------------------------------------------------------------------
__global__ void __launch_bounds__(256) stat_kernel(const float* __restrict__ x)
{
    const int row = blockIdx.x;                    // b*C + c
    const int t   = threadIdx.x;
    const float4* xr = (const float4*)(x + (size_t)row * HW_);

    float s = 0.f, ss = 0.f;
#pragma unroll
    for (int j = 0; j < 4; j++) {
        float4 q = xr[t + j * 256];                // caches in L1
        s  += (q.x + q.y) + (q.z + q.w);
        ss += q.x * q.x + q.y * q.y + q.z * q.z + q.w * q.w;
    }
#pragma unroll
    for (int o = 16; o > 0; o >>= 1) {
        s  += __shfl_xor_sync(0xffffffffu, s,  o);
        ss += __shfl_xor_sync(0xffffffffu, ss, o);
    }

    __shared__ float shS[8], shQ[8], bcast[2];
    const int w = t >> 5, l = t & 31;
    if (l == 0) { shS[w] = s; shQ[w] = ss; }
    __syncthreads();
    if (t == 0) {
        float S = 0.f, Q = 0.f;
#pragma unroll
        for (int i = 0; i < 8; i++) { S += shS[i]; Q += shQ[i]; }
        const float mean = S * (1.0f / HW_);
        const float var  = (Q - (float)HW_ * mean * mean) * (1.0f / (HW_ - 1));
        const float h4v  = 0.125f / (var + 1e-4f);   // = 0.5 * 1/(4(var+eps))
        bcast[0] = mean; bcast[1] = h4v;
        g_mean[row] = mean;
        g_h4v[row]  = h4v;
    }
    __syncthreads();
    const float mean = bcast[0];
    const float h4v  = bcast[1];

    float s2 = 0.f;
#pragma unroll
    for (int j = 0; j < 4; j++) {
        float4 q = xr[t + j * 256];                // L1 hit
        float d, th;
        d = q.x - mean; th = tanh_fast(fmaf(d * d, h4v, 0.25f)); s2 = fmaf(q.x, fmaf(th, 0.5f, 0.5f), s2);
        d = q.y - mean; th = tanh_fast(fmaf(d * d, h4v, 0.25f)); s2 = fmaf(q.y, fmaf(th, 0.5f, 0.5f), s2);
        d = q.z - mean; th = tanh_fast(fmaf(d * d, h4v, 0.25f)); s2 = fmaf(q.z, fmaf(th, 0.5f, 0.5f), s2);
        d = q.w - mean; th = tanh_fast(fmaf(d * d, h4v, 0.25f)); s2 = fmaf(q.w, fmaf(th, 0.5f, 0.5f), s2);
    }
#pragma unroll
    for (int o = 16; o > 0; o >>= 1)
        s2 += __shfl_xor_sync(0xffffffffu, s2, o);
    if (l == 0) shS[w] = s2;
    __syncthreads();
    if (t == 0) {
        float S = 0.f;
#pragma unroll
        for (int i = 0; i < 8; i++) S += shS[i];
        g_s2[row] = S;
    }
}

// ---------------------------------------------------------------------------
// Kernel 2: per-batch ECA conv + fusion MLP (tiny). One CTA per batch.
// MLP1 parallelized: 4 threads per hidden unit, shfl-reduced.
// ---------------------------------------------------------------------------
__global__ void __launch_bounds__(256) gate_kernel(const float* __restrict__ cw,
                                                   const float* __restrict__ w1,
                                                   const float* __restrict__ w2)
{
    const int b = blockIdx.x;
    const int c = threadIdx.x;        // 0..255
    const int idx = b * C_ + c;

    __shared__ float m[C_], gap[C_], hid[HID_];
    m[c] = g_mean[idx];
    __syncthreads();

    // ECA: cross-correlation over channel dim, zero-padded, K=5
    float y = 0.f;
#pragma unroll
    for (int k = 0; k < KSZ_; k++) {
        const int cc = c + k - (KSZ_ - 1) / 2;
        const float mv = (cc >= 0 && cc < C_) ? m[cc] : 0.f;
        y = fmaf(mv, cw[k], y);
    }
    const float gate = sigm(y);
    g_gate[idx] = gate;
    gap[c] = fmaf(gate, m[c], g_s2[idx] * (1.0f / HW_));
    __syncthreads();

    // hid[j] = relu(sum_c gap[c] * w1[j, c]); 4 threads per output j
    {
        const int j = c >> 2;          // 0..63
        const int p = c & 3;           // 0..3
        float h = 0.f;
        const float* w1r = w1 + j * C_ + p * 64;
        const float* gp  = gap + p * 64;
#pragma unroll 8
        for (int i = 0; i < 64; i++) h = fmaf(gp[i], w1r[i], h);
        h += __shfl_xor_sync(0xffffffffu, h, 1);
        h += __shfl_xor_sync(0xffffffffu, h, 2);
        if (p == 0) hid[j] = fmaxf(h, 0.f);
    }
    __syncthreads();

    // alpha[c] = sigmoid(sum_j hid[j] * w2[c, j]), w2 is [C, HID] row-major
    float a = 0.f;
    const float* w2r = w2 + c * HID_;
#pragma unroll 8
    for (int j = 0; j < HID_; j++) a = fmaf(hid[j], w2r[j], a);
    g_alpha[idx] = sigm(a);
}

// ---------------------------------------------------------------------------
// Kernel 3: out = x * (alpha*sigmoid(energy) + (1-alpha)*gate)
// Loads all 4 float4 up-front (MLP=4), computes, stores all 4.
// Reverse row order -> read hits on stat_kernel's L2-resident tail.
// Streaming stores keep the output from evicting x in L2.
// ---------------------------------------------------------------------------
__global__ void __launch_bounds__(256) out_kernel(const float* __restrict__ x,
                                                  float* __restrict__ out)
{
    const int row = BC_ - 1 - blockIdx.x;
    const int t   = threadIdx.x;

    const float mean  = g_mean[row];
    const float h4v   = g_h4v[row];
    const float alpha = g_alpha[row];
    const float a2    = 0.5f * alpha;
    const float a3    = fmaf(1.0f - alpha, g_gate[row], a2);

    const float4* xr = (const float4*)(x   + (size_t)row * HW_);
    float4*       ow = (float4*)     (out + (size_t)row * HW_);

    float4 q[4];
#pragma unroll
    for (int j = 0; j < 4; j++) q[j] = xr[t + j * 256];

    float4 r[4];
#pragma unroll
    for (int j = 0; j < 4; j++) {
        float d, th;
        d = q[j].x - mean; th = tanh_fast(fmaf(d * d, h4v, 0.25f)); r[j].x = q[j].x * fmaf(a2, th, a3);
        d = q[j].y - mean; th = tanh_fast(fmaf(d * d, h4v, 0.25f)); r[j].y = q[j].y * fmaf(a2, th, a3);
        d = q[j].z - mean; th = tanh_fast(fmaf(d * d, h4v, 0.25f)); r[j].z = q[j].z * fmaf(a2, th, a3);
        d = q[j].w - mean; th = tanh_fast(fmaf(d * d, h4v, 0.25f)); r[j].w = q[j].w * fmaf(a2, th, a3);
    }
#pragma unroll
    for (int j = 0; j < 4; j++) __stcs(&ow[t + j * 256], r[j]);
}

// ---------------------------------------------------------------------------
extern "C" void kernel_launch(void* const* d_in, const int* in_sizes, int n_in,
                              void* d_out, int out_size)
{
    const float* x  = (const float*)d_in[0];   // [B, C, H, W]
    const float* cw = (const float*)d_in[1];   // [1, 1, 5]
    const float* w1 = (const float*)d_in[2];   // [HID, C]
    const float* w2 = (const float*)d_in[3];   // [C, HID]
    float* out = (float*)d_out;

    stat_kernel<<<BC_, 256>>>(x);
    gate_kernel<<<B_, 256>>>(cw, w1, w2);
    out_kernel<<<BC_, 256>>>(x, out);
}